// round 5
// baseline (speedup 1.0000x reference)
#include <cuda_runtime.h>
#include <cuda_bf16.h>
#include <cstdint>
#include <cstddef>

#define NB 32
#define LQ 64
#define LV 128
#define QS 512
#define FS 1024
#define BN 512

// ---------------- scratch (device globals — no allocation) ----------------
__device__ float g_Wh[(size_t)NB * LQ * BN];
__device__ float g_Uv[(size_t)NB * LV * BN];
__device__ __nv_bfloat16 g_phr_hi[(size_t)NB * LQ * QS];
__device__ __nv_bfloat16 g_phr_lo[(size_t)NB * LQ * QS];
__device__ __nv_bfloat16 g_vis_hi[(size_t)NB * LV * FS];
__device__ __nv_bfloat16 g_vis_lo[(size_t)NB * LV * FS];
__device__ __nv_bfloat16 g_W_hi[(size_t)BN * QS];
__device__ __nv_bfloat16 g_W_lo[(size_t)BN * QS];
__device__ __nv_bfloat16 g_U_hi[(size_t)BN * FS];
__device__ __nv_bfloat16 g_U_lo[(size_t)BN * FS];
__device__ __nv_bfloat16 g_wt_hi[(size_t)NB * LQ * LV];
__device__ __nv_bfloat16 g_wt_lo[(size_t)NB * LQ * LV];

// ---------------------------------------------------------------------------
// Helpers
// ---------------------------------------------------------------------------
__device__ __forceinline__ uint32_t smem_u32(const void* p) {
    return (uint32_t)__cvta_generic_to_shared(p);
}

__device__ __forceinline__ void cpasync16(void* s, const void* g) {
    asm volatile("cp.async.cg.shared.global [%0], [%1], 16;"
                 :: "r"(smem_u32(s)), "l"(g));
}

__device__ __forceinline__ void ldsm_x4(uint32_t& r0, uint32_t& r1,
                                        uint32_t& r2, uint32_t& r3, uint32_t addr) {
    asm volatile("ldmatrix.sync.aligned.m8n8.x4.shared.b16 {%0,%1,%2,%3}, [%4];"
                 : "=r"(r0), "=r"(r1), "=r"(r2), "=r"(r3) : "r"(addr));
}

__device__ __forceinline__ void ldsm_x4_t(uint32_t& r0, uint32_t& r1,
                                          uint32_t& r2, uint32_t& r3, uint32_t addr) {
    asm volatile("ldmatrix.sync.aligned.m8n8.x4.trans.shared.b16 {%0,%1,%2,%3}, [%4];"
                 : "=r"(r0), "=r"(r1), "=r"(r2), "=r"(r3) : "r"(addr));
}

__device__ __forceinline__ void ldsm_x2(uint32_t& r0, uint32_t& r1, uint32_t addr) {
    asm volatile("ldmatrix.sync.aligned.m8n8.x2.shared.b16 {%0,%1}, [%2];"
                 : "=r"(r0), "=r"(r1) : "r"(addr));
}

__device__ __forceinline__ void mma_bf16(float* d, const uint32_t* a, const uint32_t* b) {
    asm volatile(
        "mma.sync.aligned.m16n8k16.row.col.f32.bf16.bf16.f32 "
        "{%0,%1,%2,%3}, {%4,%5,%6,%7}, {%8,%9}, {%0,%1,%2,%3};"
        : "+f"(d[0]), "+f"(d[1]), "+f"(d[2]), "+f"(d[3])
        : "r"(a[0]), "r"(a[1]), "r"(a[2]), "r"(a[3]), "r"(b[0]), "r"(b[1]));
}

// Hardware tanh: 1 MUFU op, rel err ~2^-11 (validated: net rel_err 5e-6)
__device__ __forceinline__ float tanh_fast(float x) {
    float y;
    asm("tanh.approx.f32 %0, %1;" : "=f"(y) : "f"(x));
    return y;
}

// ---------------------------------------------------------------------------
// Split pass: fp32 -> (hi, lo) bf16 for 4 arrays; also copies phr into the
// concat output columns [0, QS) (it reads phr anyway).
// ---------------------------------------------------------------------------
__global__ __launch_bounds__(256) void split4_kernel(
    const float* __restrict__ s0, __nv_bfloat16* __restrict__ h0, __nv_bfloat16* __restrict__ l0, int n0,
    const float* __restrict__ s1, __nv_bfloat16* __restrict__ h1, __nv_bfloat16* __restrict__ l1, int n1,
    const float* __restrict__ s2, __nv_bfloat16* __restrict__ h2, __nv_bfloat16* __restrict__ l2, int n2,
    const float* __restrict__ s3, __nv_bfloat16* __restrict__ h3, __nv_bfloat16* __restrict__ l3, int n3,
    float* __restrict__ out_sem)
{
    int i = blockIdx.x * 256 + threadIdx.x;
    const float* s; __nv_bfloat16 *h, *l; int idx;
    bool is_phr = false;
    if (i < n0)                { s = s0; h = h0; l = l0; idx = i; is_phr = true; }
    else if (i < n0 + n1)      { s = s1; h = h1; l = l1; idx = i - n0; }
    else if (i < n0 + n1 + n2) { s = s2; h = h2; l = l2; idx = i - n0 - n1; }
    else                       { s = s3; h = h3; l = l3; idx = i - n0 - n1 - n2; }

    float4 v = reinterpret_cast<const float4*>(s)[idx];
    __nv_bfloat162 ha, hb, la, lb;
    ha.x = __float2bfloat16(v.x); ha.y = __float2bfloat16(v.y);
    hb.x = __float2bfloat16(v.z); hb.y = __float2bfloat16(v.w);
    la.x = __float2bfloat16(v.x - __bfloat162float(ha.x));
    la.y = __float2bfloat16(v.y - __bfloat162float(ha.y));
    lb.x = __float2bfloat16(v.z - __bfloat162float(hb.x));
    lb.y = __float2bfloat16(v.w - __bfloat162float(hb.y));
    reinterpret_cast<__nv_bfloat162*>(h)[2 * idx]     = ha;
    reinterpret_cast<__nv_bfloat162*>(h)[2 * idx + 1] = hb;
    reinterpret_cast<__nv_bfloat162*>(l)[2 * idx]     = la;
    reinterpret_cast<__nv_bfloat162*>(l)[2 * idx + 1] = lb;

    if (is_phr) {
        // phr float4 idx -> concat output: row = (idx*4)/512, col = (idx*4)%512
        const size_t row = (size_t)idx >> 7;
        const int col = (idx & 127) << 2;
        *reinterpret_cast<float4*>(&out_sem[row * (QS + FS) + col]) = v;
    }
}

// ---------------------------------------------------------------------------
// Tensor-core NT GEMM on pre-split bf16 hi/lo, cp.async 2-stage pipeline.
//   C[M,N] = A[M,K] * B[N,K]^T (+ bias)   (bf16x3: hh + hl + lh)
// Block 128x64, KC=32, 256 threads = 8 warps (4x2), warp tile 32x32.
// ---------------------------------------------------------------------------
#define APITCH 40
#define KC 32
#define GSTAGE (384 * APITCH)   // halves per stage

__device__ __forceinline__ void gemm_issue_stage(
    __nv_bfloat16* smem, int st, int tid, int m0, int n0, int k0, int K,
    const __nv_bfloat16* Ahi, const __nv_bfloat16* Alo,
    const __nv_bfloat16* Bhi, const __nv_bfloat16* Blo)
{
    __nv_bfloat16* base = smem + st * GSTAGE;
#pragma unroll
    for (int e = 0; e < 2; e++) {
        int idx = tid + e * 256;
        int row = idx >> 2, c = (idx & 3) * 8;
        cpasync16(&base[row * APITCH + c], &Ahi[(size_t)(m0 + row) * K + k0 + c]);
        cpasync16(&base[128 * APITCH + row * APITCH + c],
                  &Alo[(size_t)(m0 + row) * K + k0 + c]);
    }
    {
        int row = tid >> 2, c = (tid & 3) * 8;
        cpasync16(&base[256 * APITCH + row * APITCH + c],
                  &Bhi[(size_t)(n0 + row) * K + k0 + c]);
        cpasync16(&base[320 * APITCH + row * APITCH + c],
                  &Blo[(size_t)(n0 + row) * K + k0 + c]);
    }
    asm volatile("cp.async.commit_group;");
}

__global__ __launch_bounds__(256) void gemm_nt_bf16x3(
    const __nv_bfloat16* __restrict__ Ahi, const __nv_bfloat16* __restrict__ Alo,
    const __nv_bfloat16* __restrict__ Bhi, const __nv_bfloat16* __restrict__ Blo,
    const float* __restrict__ bias, float* __restrict__ C,
    int M, int N, int K)
{
    extern __shared__ __nv_bfloat16 gsm[];

    const int tid = threadIdx.x;
    const int lane = tid & 31;
    const int wid = tid >> 5;
    const int wm = wid >> 1;
    const int wn = wid & 1;
    const int m0 = blockIdx.y * 128;
    const int n0 = blockIdx.x * 64;

    const int lq = lane >> 3;
    const int lr = lane & 7;
    const int bhalf = (lane >> 3) & 1;
    const int br = lane & 7;

    float acc[2][4][4];
#pragma unroll
    for (int i = 0; i < 2; i++)
#pragma unroll
        for (int j = 0; j < 4; j++)
#pragma unroll
            for (int r = 0; r < 4; r++) acc[i][j][r] = 0.0f;

    const int NC = K / KC;
    gemm_issue_stage(gsm, 0, tid, m0, n0, 0, K, Ahi, Alo, Bhi, Blo);

    for (int c = 0; c < NC; c++) {
        const int st = c & 1;
        if (c + 1 < NC) {
            gemm_issue_stage(gsm, st ^ 1, tid, m0, n0, (c + 1) * KC, K,
                             Ahi, Alo, Bhi, Blo);
            asm volatile("cp.async.wait_group 1;" ::: "memory");
        } else {
            asm volatile("cp.async.wait_group 0;" ::: "memory");
        }
        __syncthreads();

        const __nv_bfloat16* Ah_s = gsm + st * GSTAGE;
        const __nv_bfloat16* Al_s = Ah_s + 128 * APITCH;
        const __nv_bfloat16* Bh_s = Ah_s + 256 * APITCH;
        const __nv_bfloat16* Bl_s = Ah_s + 320 * APITCH;

#pragma unroll
        for (int ks = 0; ks < KC; ks += 16) {
            uint32_t ah[2][4], al[2][4];
#pragma unroll
            for (int ma = 0; ma < 2; ma++) {
                const int m_local = wm * 32 + ma * 16 + (lq & 1) * 8 + lr;
                const int k_local = ks + (lq >> 1) * 8;
                ldsm_x4(ah[ma][0], ah[ma][1], ah[ma][2], ah[ma][3],
                        smem_u32(&Ah_s[m_local * APITCH + k_local]));
                ldsm_x4(al[ma][0], al[ma][1], al[ma][2], al[ma][3],
                        smem_u32(&Al_s[m_local * APITCH + k_local]));
            }
            uint32_t bh[4][2], bl[4][2];
#pragma unroll
            for (int na = 0; na < 4; na++) {
                const int n_local = wn * 32 + na * 8 + br;
                const int k_local = ks + bhalf * 8;
                ldsm_x2(bh[na][0], bh[na][1],
                        smem_u32(&Bh_s[n_local * APITCH + k_local]));
                ldsm_x2(bl[na][0], bl[na][1],
                        smem_u32(&Bl_s[n_local * APITCH + k_local]));
            }
#pragma unroll
            for (int ma = 0; ma < 2; ma++)
#pragma unroll
                for (int na = 0; na < 4; na++) {
                    mma_bf16(acc[ma][na], ah[ma], bh[na]);
                    mma_bf16(acc[ma][na], ah[ma], bl[na]);
                    mma_bf16(acc[ma][na], al[ma], bh[na]);
                }
        }
        __syncthreads();
    }

    const int er = lane >> 2;
    const int ec = (lane & 3) << 1;
#pragma unroll
    for (int ma = 0; ma < 2; ma++) {
        const int mbase = m0 + wm * 32 + ma * 16;
#pragma unroll
        for (int na = 0; na < 4; na++) {
            const int nbase = n0 + wn * 32 + na * 8 + ec;
            float b0 = 0.0f, b1 = 0.0f;
            if (bias) { b0 = bias[nbase]; b1 = bias[nbase + 1]; }
            float2 v0, v1;
            v0.x = acc[ma][na][0] + b0; v0.y = acc[ma][na][1] + b1;
            v1.x = acc[ma][na][2] + b0; v1.y = acc[ma][na][3] + b1;
            *reinterpret_cast<float2*>(&C[(size_t)(mbase + er) * N + nbase]) = v0;
            *reinterpret_cast<float2*>(&C[(size_t)(mbase + er + 8) * N + nbase]) = v1;
        }
    }
}

// ---------------------------------------------------------------------------
// Fused energies + softmax, n-split 2x for occupancy.
// Block: 4 q rows x 128 v, 8 warps. Warp w: q_local = w>>1, n-half = w&1.
// Each warp reduces its 256-n half; halves combined via smem; half-0 warps
// do the in-register softmax and write all outputs.
// Grid: (LQ/4, NB) = 512 CTAs -> ~43% occupancy (vs 20% before).
// ---------------------------------------------------------------------------
#define EQT 4

__global__ __launch_bounds__(256) void energy_softmax_kernel(
    const float* __restrict__ Wh, const float* __restrict__ Uv,
    const float* __restrict__ w,
    float* __restrict__ energies, float* __restrict__ weights,
    __nv_bfloat16* __restrict__ wt_hi, __nv_bfloat16* __restrict__ wt_lo)
{
    __shared__ float As[2][16][EQT];     // [half][kk][q]
    __shared__ float Cs[2][16][132];     // [half][kk][v]
    __shared__ float ws[BN];
    __shared__ float red[EQT][LV];       // partial-sum exchange

    const int b = blockIdx.y;
    const int q0 = blockIdx.x * EQT;
    const int tid = threadIdx.x;
    const int lane = tid & 31;
    const int wid = tid >> 5;
    const int ql = wid >> 1;     // local q row 0..3
    const int h = wid & 1;       // n-half

    const float* Ab = Wh + ((size_t)b * LQ + q0) * BN;
    const float* Cb = Uv + (size_t)b * LV * BN;

    for (int i = tid; i < BN; i += 256) ws[i] = w[i];

    float acc[4] = {0.0f, 0.0f, 0.0f, 0.0f};

    for (int it = 0; it < 16; it++) {
        // stage As: 2 halves x 16 kk x 4 q = 128
        if (tid < 128) {
            const int hh = tid >> 6;
            const int kk = (tid >> 2) & 15;
            const int q = tid & 3;
            As[hh][kk][q] = Ab[(size_t)q * BN + hh * 256 + it * 16 + kk];
        }
        // stage Cs: 2 halves x 16 kk x 128 v = 4096
#pragma unroll
        for (int e = 0; e < 16; e++) {
            const int id = tid + e * 256;
            const int hh = id >> 11;
            const int r = id & 2047;
            const int v = r >> 4, kk = r & 15;
            Cs[hh][kk][v] = Cb[(size_t)v * BN + hh * 256 + it * 16 + kk];
        }
        __syncthreads();
        const int nbase = h * 256 + it * 16;
#pragma unroll
        for (int kk = 0; kk < 16; kk++) {
            const float a = As[h][kk][ql];
            const float wn = ws[nbase + kk];
#pragma unroll
            for (int j = 0; j < 4; j++)
                acc[j] += wn * tanh_fast(a + Cs[h][kk][lane + 32 * j]);
        }
        __syncthreads();
    }

    // combine the two n-halves
    if (h == 1) {
#pragma unroll
        for (int j = 0; j < 4; j++) red[ql][lane + 32 * j] = acc[j];
    }
    __syncthreads();
    if (h == 0) {
#pragma unroll
        for (int j = 0; j < 4; j++) acc[j] += red[ql][lane + 32 * j];

        // warp softmax over 128 v (4 per lane)
        float mx = fmaxf(fmaxf(acc[0], acc[1]), fmaxf(acc[2], acc[3]));
#pragma unroll
        for (int o = 16; o > 0; o >>= 1)
            mx = fmaxf(mx, __shfl_xor_sync(0xFFFFFFFFu, mx, o));
        float ex[4], s = 0.0f;
#pragma unroll
        for (int j = 0; j < 4; j++) { ex[j] = __expf(acc[j] - mx); s += ex[j]; }
#pragma unroll
        for (int o = 16; o > 0; o >>= 1)
            s += __shfl_xor_sync(0xFFFFFFFFu, s, o);
        const float inv = __fdividef(1.0f, s);

        const size_t row = (size_t)b * LQ + q0 + ql;
#pragma unroll
        for (int j = 0; j < 4; j++) {
            const size_t o = row * LV + lane + 32 * j;
            const float wv = ex[j] * inv;
            energies[o] = acc[j];
            weights[o] = wv;
            __nv_bfloat16 hh = __float2bfloat16(wv);
            wt_hi[o] = hh;
            wt_lo[o] = __float2bfloat16(wv - __bfloat162float(hh));
        }
    }
}

// ---------------------------------------------------------------------------
// Tensor-core aligned: out[b,q,QS+f] = sum_v weights[b,q,v] * vis[b,v,f]
// bf16x3 on weights hi/lo and pre-split vis hi/lo. Block: 64q x 128f, K=128.
// ---------------------------------------------------------------------------
#define WPITCH 136

__global__ __launch_bounds__(256) void aligned_tc_kernel(
    const __nv_bfloat16* __restrict__ wt_hi, const __nv_bfloat16* __restrict__ wt_lo,
    const __nv_bfloat16* __restrict__ vis_hi, const __nv_bfloat16* __restrict__ vis_lo,
    float* __restrict__ out_sem)
{
    extern __shared__ __nv_bfloat16 asm_[];
    __nv_bfloat16* Wh_s = asm_;
    __nv_bfloat16* Wl_s = asm_ + 64 * WPITCH;
    __nv_bfloat16* Vh_s = asm_ + 128 * WPITCH;
    __nv_bfloat16* Vl_s = asm_ + 256 * WPITCH;

    const int b = blockIdx.y;
    const int f0 = blockIdx.x * 128;
    const int tid = threadIdx.x;
    const int lane = tid & 31;
    const int wid = tid >> 5;
    const int wm = wid >> 2;
    const int wn = wid & 3;
    const int lq = lane >> 3;
    const int lr = lane & 7;

#pragma unroll
    for (int e = 0; e < 4; e++) {
        int idx = tid + e * 256;
        int row = idx >> 4, c = (idx & 15) * 8;
        cpasync16(&Wh_s[row * WPITCH + c], &wt_hi[((size_t)b * LQ + row) * LV + c]);
        cpasync16(&Wl_s[row * WPITCH + c], &wt_lo[((size_t)b * LQ + row) * LV + c]);
    }
#pragma unroll
    for (int e = 0; e < 8; e++) {
        int idx = tid + e * 256;
        int row = idx >> 4, c = (idx & 15) * 8;
        cpasync16(&Vh_s[row * WPITCH + c],
                  &vis_hi[((size_t)b * LV + row) * FS + f0 + c]);
        cpasync16(&Vl_s[row * WPITCH + c],
                  &vis_lo[((size_t)b * LV + row) * FS + f0 + c]);
    }
    asm volatile("cp.async.commit_group;");
    asm volatile("cp.async.wait_group 0;" ::: "memory");
    __syncthreads();

    float acc[2][4][4];
#pragma unroll
    for (int i = 0; i < 2; i++)
#pragma unroll
        for (int j = 0; j < 4; j++)
#pragma unroll
            for (int r = 0; r < 4; r++) acc[i][j][r] = 0.0f;

#pragma unroll
    for (int ks = 0; ks < 8; ks++) {
        uint32_t ah[2][4], al[2][4];
#pragma unroll
        for (int ma = 0; ma < 2; ma++) {
            const int m_local = wm * 32 + ma * 16 + (lq & 1) * 8 + lr;
            const int k_local = ks * 16 + (lq >> 1) * 8;
            ldsm_x4(ah[ma][0], ah[ma][1], ah[ma][2], ah[ma][3],
                    smem_u32(&Wh_s[m_local * WPITCH + k_local]));
            ldsm_x4(al[ma][0], al[ma][1], al[ma][2], al[ma][3],
                    smem_u32(&Wl_s[m_local * WPITCH + k_local]));
        }
        uint32_t bh[4][2], bl[4][2];
#pragma unroll
        for (int np = 0; np < 2; np++) {
            const int krow = ks * 16 + (lq & 1) * 8 + lr;
            const int ncol = wn * 32 + np * 16 + (lq >> 1) * 8;
            uint32_t r0, r1, r2, r3;
            ldsm_x4_t(r0, r1, r2, r3, smem_u32(&Vh_s[krow * WPITCH + ncol]));
            bh[np * 2][0] = r0; bh[np * 2][1] = r1;
            bh[np * 2 + 1][0] = r2; bh[np * 2 + 1][1] = r3;
            ldsm_x4_t(r0, r1, r2, r3, smem_u32(&Vl_s[krow * WPITCH + ncol]));
            bl[np * 2][0] = r0; bl[np * 2][1] = r1;
            bl[np * 2 + 1][0] = r2; bl[np * 2 + 1][1] = r3;
        }
#pragma unroll
        for (int ma = 0; ma < 2; ma++)
#pragma unroll
            for (int na = 0; na < 4; na++) {
                mma_bf16(acc[ma][na], ah[ma], bh[na]);
                mma_bf16(acc[ma][na], ah[ma], bl[na]);
                mma_bf16(acc[ma][na], al[ma], bh[na]);
            }
    }

    const int er = lane >> 2;
    const int ec = (lane & 3) << 1;
#pragma unroll
    for (int ma = 0; ma < 2; ma++) {
        const int qbase = wm * 32 + ma * 16;
#pragma unroll
        for (int na = 0; na < 4; na++) {
            const int f = f0 + wn * 32 + na * 8 + ec;
            float2 v0, v1;
            v0.x = acc[ma][na][0]; v0.y = acc[ma][na][1];
            v1.x = acc[ma][na][2]; v1.y = acc[ma][na][3];
            *reinterpret_cast<float2*>(
                &out_sem[((size_t)b * LQ + qbase + er) * (QS + FS) + QS + f]) = v0;
            *reinterpret_cast<float2*>(
                &out_sem[((size_t)b * LQ + qbase + er + 8) * (QS + FS) + QS + f]) = v1;
        }
    }
}

extern "C" void kernel_launch(void* const* d_in, const int* in_sizes, int n_in,
                              void* d_out, int out_size)
{
    const float* phr  = (const float*)d_in[0];
    const float* vis  = (const float*)d_in[1];
    const float* W    = (const float*)d_in[2];
    const float* U    = (const float*)d_in[3];
    const float* bias = (const float*)d_in[4];
    const float* w    = (const float*)d_in[5];

    float* out = (float*)d_out;
    float* out_sem = out;
    float* out_w   = out + (size_t)NB * LQ * (QS + FS);
    float* out_e   = out_w + (size_t)NB * LQ * LV;

    float *Wh, *Uv;
    __nv_bfloat16 *phr_hi, *phr_lo, *vis_hi, *vis_lo, *W_hi, *W_lo, *U_hi, *U_lo;
    __nv_bfloat16 *wt_hi, *wt_lo;
    cudaGetSymbolAddress((void**)&Wh, g_Wh);
    cudaGetSymbolAddress((void**)&Uv, g_Uv);
    cudaGetSymbolAddress((void**)&phr_hi, g_phr_hi);
    cudaGetSymbolAddress((void**)&phr_lo, g_phr_lo);
    cudaGetSymbolAddress((void**)&vis_hi, g_vis_hi);
    cudaGetSymbolAddress((void**)&vis_lo, g_vis_lo);
    cudaGetSymbolAddress((void**)&W_hi, g_W_hi);
    cudaGetSymbolAddress((void**)&W_lo, g_W_lo);
    cudaGetSymbolAddress((void**)&U_hi, g_U_hi);
    cudaGetSymbolAddress((void**)&U_lo, g_U_lo);
    cudaGetSymbolAddress((void**)&wt_hi, g_wt_hi);
    cudaGetSymbolAddress((void**)&wt_lo, g_wt_lo);

    cudaFuncSetAttribute(gemm_nt_bf16x3,
                         cudaFuncAttributeMaxDynamicSharedMemorySize, 61440);
    cudaFuncSetAttribute(aligned_tc_kernel,
                         cudaFuncAttributeMaxDynamicSharedMemorySize, 104448);

    // split (+ phr concat copy): phr(262144 f4), vis(1048576), W(65536), U(131072)
    split4_kernel<<<5888, 256>>>(phr, phr_hi, phr_lo, 262144,
                                 vis, vis_hi, vis_lo, 1048576,
                                 W,   W_hi,   W_lo,   65536,
                                 U,   U_hi,   U_lo,   131072,
                                 out_sem);

    // Wh = phr @ W^T + b   (M=2048, N=512, K=512)
    gemm_nt_bf16x3<<<dim3(BN / 64, (NB * LQ) / 128), 256, 61440>>>(
        phr_hi, phr_lo, W_hi, W_lo, bias, Wh, NB * LQ, BN, QS);
    // Uv = vis @ U^T       (M=4096, N=512, K=1024)
    gemm_nt_bf16x3<<<dim3(BN / 64, (NB * LV) / 128), 256, 61440>>>(
        vis_hi, vis_lo, U_hi, U_lo, nullptr, Uv, NB * LV, BN, FS);

    // energies + softmax (n-split 2x, 512 CTAs)
    energy_softmax_kernel<<<dim3(LQ / EQT, NB), 256>>>(Wh, Uv, w, out_e, out_w,
                                                       wt_hi, wt_lo);
    // aligned via tensor cores
    aligned_tc_kernel<<<dim3(FS / 128, NB), 256, 104448>>>(wt_hi, wt_lo,
                                                           vis_hi, vis_lo,
                                                           out_sem);
}